// round 1
// baseline (speedup 1.0000x reference)
#include <cuda_runtime.h>

#define LDIM 26
#define KCOMP 64
#define BN 262144
#define NITER 8
#define WFLOOR 1e-5f
#define VFLOOR 1e-6f
#define LOG_PI_C 47.784803726642978f   // 26 * log(2*pi)

#define NBLK_A 592            // estep blocks (256 thr = 8 warps each)
#define NBLK_B 296            // mstat blocks
#define STAT 53               // 1 (z) + 26 (px) + 26 (pxx)
#define PTOT (NBLK_B * 4)     // partial accumulator slots
#define TILES (BN / 32)
#define OUT_N (KCOMP + KCOMP*LDIM + KCOMP*LDIM*LDIM + 1)   // 44993

// ---------------- device state (no allocation allowed) ----------------
__device__ float g_w[KCOMP];
__device__ float g_mu[KCOMP * LDIM];
__device__ float g_sig[KCOMP * LDIM];
__device__ float g_Ph[KCOMP * LDIM];     // 0.5 / sigma
__device__ float g_MP[KCOMP * LDIM];     // mu / sigma
__device__ float g_C[KCOMP];             // log w - 0.5*(LOG_PI + logdet + quad)
__device__ float g_post[BN * KCOMP];     // 64 MiB posterior scratch
__device__ float g_part[PTOT * KCOMP * STAT];
__device__ float g_llp[NBLK_A];
__device__ float g_ll;

// ---------------- init: normalize w0, copy mu0 / sigma0 ----------------
__global__ void k_init(const float* __restrict__ w0,
                       const float* __restrict__ mu0,
                       const float* __restrict__ s0) {
    __shared__ float s_sum;
    if (threadIdx.x == 0) {
        float s = 0.f;
        for (int k = 0; k < KCOMP; k++) s += w0[k];
        s_sum = s;
    }
    __syncthreads();
    for (int i = threadIdx.x; i < KCOMP * LDIM; i += blockDim.x) {
        g_mu[i]  = mu0[i];
        g_sig[i] = s0[i];
    }
    if (threadIdx.x < KCOMP) g_w[threadIdx.x] = w0[threadIdx.x] / s_sum;
}

// ---------------- prep: per-component E-step params ----------------
__global__ void k_prep() {
    int k = blockIdx.x;
    int lane = threadIdx.x;
    float ld = 0.f, qd = 0.f;
    if (lane < LDIM) {
        float sg = g_sig[k * LDIM + lane];
        float mu = g_mu[k * LDIM + lane];
        float pr = 1.0f / sg;
        g_Ph[k * LDIM + lane] = 0.5f * pr;
        g_MP[k * LDIM + lane] = mu * pr;
        ld = logf(sg);
        qd = mu * mu * pr;
    }
    #pragma unroll
    for (int o = 16; o; o >>= 1) {
        ld += __shfl_xor_sync(0xffffffffu, ld, o);
        qd += __shfl_xor_sync(0xffffffffu, qd, o);
    }
    if (lane == 0)
        g_C[k] = logf(g_w[k]) - 0.5f * (LOG_PI_C + ld + qd);
}

// ---------------- E-step: warp per row, lane owns k and k+32 ----------------
__global__ void __launch_bounds__(256) k_estep(const float* __restrict__ x) {
    int lane = threadIdx.x & 31;
    int warp = (blockIdx.x * 256 + threadIdx.x) >> 5;
    const int nwarps = NBLK_A * 8;

    float Ph0[LDIM], MP0[LDIM], Ph1[LDIM], MP1[LDIM];
    #pragma unroll
    for (int l = 0; l < LDIM; l++) {
        Ph0[l] = g_Ph[lane * LDIM + l];
        MP0[l] = g_MP[lane * LDIM + l];
        Ph1[l] = g_Ph[(lane + 32) * LDIM + l];
        MP1[l] = g_MP[(lane + 32) * LDIM + l];
    }
    float C0 = g_C[lane], C1 = g_C[lane + 32];

    float llacc = 0.f;
    for (int row = warp; row < BN; row += nwarps) {
        float xv = (lane < LDIM) ? x[row * LDIM + lane] : 0.f;
        float n0 = C0, n1 = C1;
        #pragma unroll
        for (int l = 0; l < LDIM; l++) {
            float xl = __shfl_sync(0xffffffffu, xv, l);
            float x2 = xl * xl;
            n0 = fmaf(xl, MP0[l], n0);
            n1 = fmaf(xl, MP1[l], n1);
            n0 = fmaf(-x2, Ph0[l], n0);
            n1 = fmaf(-x2, Ph1[l], n1);
        }
        float m = fmaxf(n0, n1);
        #pragma unroll
        for (int o = 16; o; o >>= 1) m = fmaxf(m, __shfl_xor_sync(0xffffffffu, m, o));
        float e0 = __expf(n0 - m);
        float e1 = __expf(n1 - m);
        float s = e0 + e1;
        #pragma unroll
        for (int o = 16; o; o >>= 1) s += __shfl_xor_sync(0xffffffffu, s, o);
        float rs = __frcp_rn(s);
        g_post[row * KCOMP + lane]      = e0 * rs;
        g_post[row * KCOMP + lane + 32] = e1 * rs;
        if (lane == 0) llacc += __logf(s) + m;
    }

    __shared__ float s_ll[8];
    if (lane == 0) s_ll[threadIdx.x >> 5] = llacc;
    __syncthreads();
    if (threadIdx.x == 0) {
        float t = 0.f;
        for (int i = 0; i < 8; i++) t += s_ll[i];
        g_llp[blockIdx.x] = t;
    }
}

// ---------------- M-step stats: posterior^T @ [1|x|x^2] partials ----------------
__global__ void __launch_bounds__(256) k_mstat(const float* __restrict__ x) {
    __shared__ float xs[32][LDIM];
    __shared__ float x2s[32][LDIM];
    int tid = threadIdx.x;
    int k = tid & 63;
    int g = tid >> 6;     // 0..3

    float acc[STAT];
    #pragma unroll
    for (int j = 0; j < STAT; j++) acc[j] = 0.f;

    for (int t = blockIdx.x; t < TILES; t += NBLK_B) {
        int rowbase = t * 32;
        __syncthreads();
        for (int i = tid; i < 32 * LDIM; i += 256) {
            float v = x[rowbase * LDIM + i];
            int r = i / LDIM, c = i % LDIM;
            xs[r][c] = v;
            x2s[r][c] = v * v;
        }
        __syncthreads();
        #pragma unroll
        for (int rr = 0; rr < 8; rr++) {
            int r = g + rr * 4;
            float p = g_post[(rowbase + r) * KCOMP + k];
            acc[0] += p;
            #pragma unroll
            for (int l = 0; l < LDIM; l++)
                acc[1 + l] = fmaf(p, xs[r][l], acc[1 + l]);
            #pragma unroll
            for (int l = 0; l < LDIM; l++)
                acc[27 + l] = fmaf(p, x2s[r][l], acc[27 + l]);
        }
    }
    int pidx = blockIdx.x * 4 + g;
    float* dst = &g_part[(pidx * KCOMP + k) * STAT];
    #pragma unroll
    for (int j = 0; j < STAT; j++) dst[j] = acc[j];
}

// ---------------- M-step finalize: reduce partials, update w/mu/sig, ll ----------------
__global__ void __launch_bounds__(1024) k_mstep() {
    __shared__ float s_stat[KCOMP * STAT];
    __shared__ float s_w[KCOMP];
    __shared__ float s_ab[2];
    int tid = threadIdx.x;

    for (int idx = tid; idx < KCOMP * STAT; idx += 1024) {
        float s = 0.f;
        for (int p = 0; p < PTOT; p++) s += g_part[p * (KCOMP * STAT) + idx];
        s_stat[idx] = s;
    }
    __syncthreads();

    if (tid < KCOMP) s_w[tid] = fmaxf(s_stat[tid * STAT] * (1.0f / BN), WFLOOR);
    __syncthreads();

    if (tid == 0) {
        float sum = 0.f;
        for (int k = 0; k < KCOMP; k++) sum += s_w[k];
        float sf = WFLOOR * KCOMP;
        float a = (1.0f - sf) / (sum - sf);
        s_ab[0] = a;
        s_ab[1] = WFLOOR * (1.0f - a);
        float ll = 0.f;
        for (int i = 0; i < NBLK_A; i++) ll += g_llp[i];
        g_ll = ll;
    }
    __syncthreads();

    if (tid < KCOMP) g_w[tid] = s_ab[0] * s_w[tid] + s_ab[1];

    for (int idx = tid; idx < KCOMP * LDIM; idx += 1024) {
        int k = idx / LDIM, l = idx % LDIM;
        float z = s_stat[k * STAT];
        float zi = 1.0f / z;
        float mu = s_stat[k * STAT + 1 + l] * zi;
        float sg = fmaxf(s_stat[k * STAT + 27 + l] * zi - mu * mu, VFLOOR);
        g_mu[idx] = mu;
        g_sig[idx] = sg;
    }
}

// ---------------- output: w | mu | diag-expanded sigma | ll ----------------
__global__ void k_write(float* __restrict__ out) {
    int i = blockIdx.x * 256 + threadIdx.x;
    if (i >= OUT_N) return;
    float v;
    if (i < KCOMP) {
        v = g_w[i];
    } else if (i < KCOMP + KCOMP * LDIM) {
        v = g_mu[i - KCOMP];
    } else if (i < KCOMP + KCOMP * LDIM + KCOMP * LDIM * LDIM) {
        int j = i - (KCOMP + KCOMP * LDIM);
        int k = j / (LDIM * LDIM);
        int rc = j % (LDIM * LDIM);
        int r = rc / LDIM, c = rc % LDIM;
        v = (r == c) ? g_sig[k * LDIM + r] : 0.f;
    } else {
        v = g_ll;
    }
    out[i] = v;
}

extern "C" void kernel_launch(void* const* d_in, const int* in_sizes, int n_in,
                              void* d_out, int out_size) {
    const float* x   = (const float*)d_in[0];
    const float* w0  = (const float*)d_in[1];
    const float* mu0 = (const float*)d_in[2];
    const float* s0  = (const float*)d_in[3];
    float* out = (float*)d_out;

    k_init<<<1, 256>>>(w0, mu0, s0);
    k_prep<<<KCOMP, 32>>>();
    for (int it = 0; it < NITER; it++) {
        k_estep<<<NBLK_A, 256>>>(x);
        k_mstat<<<NBLK_B, 256>>>(x);
        k_mstep<<<1, 1024>>>();
        k_prep<<<KCOMP, 32>>>();
    }
    k_write<<<(OUT_N + 255) / 256, 256>>>(out);
}

// round 2
// speedup vs baseline: 1.5648x; 1.5648x over previous
#include <cuda_runtime.h>

#define LDIM 26
#define KCOMP 64
#define BN 262144
#define NITER 8
#define WFLOOR 1e-5f
#define VFLOOR 1e-6f
#define LOG_PI_C 47.784803726642978f   // 26 * log(2*pi)

#define NBLK_E 444            // estep blocks (128 thr = 4 warps)
#define TILE_E 64
#define NBLK_M 296            // mstat blocks (512 thr)
#define TILE_M 32
#define NSLOT (NBLK_M * 4)    // partial slots per h (block x group)
#define NST 29                // z + 28 (26 real + 2 pad) accumulators
#define OUT_N (KCOMP + KCOMP*LDIM + KCOMP*LDIM*LDIM + 1)   // 44993

// ---------------- device state (no allocation allowed) ----------------
__device__ float g_w[KCOMP];
__device__ float g_mu[KCOMP * LDIM];
__device__ float g_sig[KCOMP * LDIM];
__device__ float g_Ph[KCOMP * LDIM];     // 0.5 / sigma
__device__ float g_MP[KCOMP * LDIM];     // mu / sigma
__device__ float g_C[KCOMP];             // log w - 0.5*(LOG_PI + logdet + quad)
__device__ float g_post[BN * KCOMP];     // 64 MiB posterior scratch
__device__ float g_part[2 * NSLOT * KCOMP * NST];   // h-split partials
__device__ float g_stat[2 * KCOMP * NST];           // reduced stats
__device__ float g_llp[NBLK_E];
__device__ float g_ll;

// ---------------- init: normalize w0, copy mu0 / sigma0 ----------------
__global__ void k_init(const float* __restrict__ w0,
                       const float* __restrict__ mu0,
                       const float* __restrict__ s0) {
    __shared__ float s_sum;
    if (threadIdx.x == 0) {
        float s = 0.f;
        for (int k = 0; k < KCOMP; k++) s += w0[k];
        s_sum = s;
    }
    __syncthreads();
    for (int i = threadIdx.x; i < KCOMP * LDIM; i += blockDim.x) {
        g_mu[i]  = mu0[i];
        g_sig[i] = s0[i];
    }
    if (threadIdx.x < KCOMP) g_w[threadIdx.x] = w0[threadIdx.x] / s_sum;
}

// ---------------- prep: per-component E-step params ----------------
__global__ void k_prep() {
    int k = blockIdx.x;
    int lane = threadIdx.x;
    float ld = 0.f, qd = 0.f;
    if (lane < LDIM) {
        float sg = g_sig[k * LDIM + lane];
        float mu = g_mu[k * LDIM + lane];
        float pr = 1.0f / sg;
        g_Ph[k * LDIM + lane] = 0.5f * pr;
        g_MP[k * LDIM + lane] = mu * pr;
        ld = logf(sg);
        qd = mu * mu * pr;
    }
    #pragma unroll
    for (int o = 16; o; o >>= 1) {
        ld += __shfl_xor_sync(0xffffffffu, ld, o);
        qd += __shfl_xor_sync(0xffffffffu, qd, o);
    }
    if (lane == 0)
        g_C[k] = logf(g_w[k]) - 0.5f * (LOG_PI_C + ld + qd);
}

// ---------------- E-step: warp-per-row from smem tile, lane owns k and k+32 ----
__global__ void __launch_bounds__(128) k_estep(const float* __restrict__ x) {
    __shared__ float xt[TILE_E * 52];       // per row: 13 x float4 (x,x2,x,x2)
    __shared__ float sll[4];
    int tid = threadIdx.x;
    int lane = tid & 31;
    int warp = tid >> 5;

    float MP0[LDIM], Ph0[LDIM], MP1[LDIM], Ph1[LDIM];
    #pragma unroll
    for (int l = 0; l < LDIM; l++) {
        MP0[l] = g_MP[lane * LDIM + l];
        Ph0[l] = g_Ph[lane * LDIM + l];
        MP1[l] = g_MP[(lane + 32) * LDIM + l];
        Ph1[l] = g_Ph[(lane + 32) * LDIM + l];
    }
    float C0 = g_C[lane], C1 = g_C[lane + 32];
    float llacc = 0.f;

    for (int t = blockIdx.x; t < BN / TILE_E; t += NBLK_E) {
        int rowbase = t * TILE_E;
        __syncthreads();
        for (int i = tid; i < TILE_E * LDIM; i += 128) {
            int r = i / LDIM, c = i % LDIM;
            float v = x[(rowbase + r) * LDIM + c];
            int off = r * 52 + (c >> 1) * 4 + ((c & 1) << 1);
            xt[off] = v;
            xt[off + 1] = v * v;
        }
        __syncthreads();
        #pragma unroll 1
        for (int it = 0; it < 8; it++) {
            int r0 = warp * 16 + it * 2;
            int r1 = r0 + 1;
            const float4* a4 = (const float4*)(xt + r0 * 52);
            const float4* b4 = (const float4*)(xt + r1 * 52);
            float n00 = C0, n01 = C1, n10 = C0, n11 = C1;
            #pragma unroll
            for (int i = 0; i < 13; i++) {
                float4 a = a4[i];
                float4 b = b4[i];
                n00 = fmaf(a.x, MP0[2*i],   n00);
                n00 = fmaf(-a.y, Ph0[2*i],  n00);
                n00 = fmaf(a.z, MP0[2*i+1], n00);
                n00 = fmaf(-a.w, Ph0[2*i+1],n00);
                n01 = fmaf(a.x, MP1[2*i],   n01);
                n01 = fmaf(-a.y, Ph1[2*i],  n01);
                n01 = fmaf(a.z, MP1[2*i+1], n01);
                n01 = fmaf(-a.w, Ph1[2*i+1],n01);
                n10 = fmaf(b.x, MP0[2*i],   n10);
                n10 = fmaf(-b.y, Ph0[2*i],  n10);
                n10 = fmaf(b.z, MP0[2*i+1], n10);
                n10 = fmaf(-b.w, Ph0[2*i+1],n10);
                n11 = fmaf(b.x, MP1[2*i],   n11);
                n11 = fmaf(-b.y, Ph1[2*i],  n11);
                n11 = fmaf(b.z, MP1[2*i+1], n11);
                n11 = fmaf(-b.w, Ph1[2*i+1],n11);
            }
            float m0 = fmaxf(n00, n01);
            float m1 = fmaxf(n10, n11);
            #pragma unroll
            for (int o = 16; o; o >>= 1) {
                m0 = fmaxf(m0, __shfl_xor_sync(0xffffffffu, m0, o));
                m1 = fmaxf(m1, __shfl_xor_sync(0xffffffffu, m1, o));
            }
            float e00 = __expf(n00 - m0);
            float e01 = __expf(n01 - m0);
            float e10 = __expf(n10 - m1);
            float e11 = __expf(n11 - m1);
            float s0 = e00 + e01;
            float s1 = e10 + e11;
            #pragma unroll
            for (int o = 16; o; o >>= 1) {
                s0 += __shfl_xor_sync(0xffffffffu, s0, o);
                s1 += __shfl_xor_sync(0xffffffffu, s1, o);
            }
            float rs0 = __frcp_rn(s0);
            float rs1 = __frcp_rn(s1);
            int gr0 = rowbase + r0, gr1 = rowbase + r1;
            g_post[gr0 * KCOMP + lane]      = e00 * rs0;
            g_post[gr0 * KCOMP + lane + 32] = e01 * rs0;
            g_post[gr1 * KCOMP + lane]      = e10 * rs1;
            g_post[gr1 * KCOMP + lane + 32] = e11 * rs1;
            if (lane == 0) llacc += __logf(s0) + m0 + __logf(s1) + m1;
        }
    }
    if (lane == 0) sll[warp] = llacc;
    __syncthreads();
    if (tid == 0) {
        float t = 0.f;
        for (int i = 0; i < 4; i++) t += sll[i];
        g_llp[blockIdx.x] = t;
    }
}

// ---------------- M-step stats: h-split posterior^T @ [1|x] and [1|x^2] ------
__global__ void __launch_bounds__(512) k_mstat(const float* __restrict__ x) {
    __shared__ float xs[TILE_M * 28];
    __shared__ float x2s[TILE_M * 28];
    int tid = threadIdx.x;
    int k = tid & 63;
    int g = (tid >> 6) & 3;
    int h = tid >> 8;           // 0: x stats, 1: x^2 stats (uniform per warp)
    if (tid < TILE_M) {
        xs[tid * 28 + 26] = 0.f;  xs[tid * 28 + 27] = 0.f;
        x2s[tid * 28 + 26] = 0.f; x2s[tid * 28 + 27] = 0.f;
    }
    const float* sb = h ? x2s : xs;

    float z = 0.f;
    float acc[28];
    #pragma unroll
    for (int j = 0; j < 28; j++) acc[j] = 0.f;

    for (int t = blockIdx.x; t < BN / TILE_M; t += NBLK_M) {
        int rowbase = t * TILE_M;
        __syncthreads();
        for (int i = tid; i < TILE_M * LDIM; i += 512) {
            int r = i / LDIM, c = i % LDIM;
            float v = x[(rowbase + r) * LDIM + c];
            xs[r * 28 + c] = v;
            x2s[r * 28 + c] = v * v;
        }
        __syncthreads();
        #pragma unroll
        for (int rr = 0; rr < 8; rr++) {
            int r = g * 8 + rr;
            float p = g_post[(rowbase + r) * KCOMP + k];
            z += p;
            const float4* v4 = (const float4*)(sb + r * 28);
            #pragma unroll
            for (int i = 0; i < 7; i++) {
                float4 v = v4[i];
                acc[4*i]   = fmaf(p, v.x, acc[4*i]);
                acc[4*i+1] = fmaf(p, v.y, acc[4*i+1]);
                acc[4*i+2] = fmaf(p, v.z, acc[4*i+2]);
                acc[4*i+3] = fmaf(p, v.w, acc[4*i+3]);
            }
        }
    }
    int slot = blockIdx.x * 4 + g;
    float* dst = g_part + ((size_t)(h * NSLOT + slot) * KCOMP + k) * NST;
    dst[0] = z;
    #pragma unroll
    for (int j = 0; j < 28; j++) dst[1 + j] = acc[j];
}

// ---------------- reduce partials: one block per (k, h) ----------------
__global__ void __launch_bounds__(256) k_reduce() {
    __shared__ float red[8][NST];
    int bk = blockIdx.x & 63;
    int h = blockIdx.x >> 6;
    int tid = threadIdx.x;
    if (tid < 8 * NST) {
        int c = tid / NST;
        int j = tid % NST;
        float s = 0.f;
        for (int slot = c; slot < NSLOT; slot += 8)
            s += g_part[((size_t)(h * NSLOT + slot) * KCOMP + bk) * NST + j];
        red[c][j] = s;
    }
    __syncthreads();
    if (tid < NST) {
        float s = 0.f;
        for (int c = 0; c < 8; c++) s += red[c][tid];
        g_stat[(h * KCOMP + bk) * NST + tid] = s;
    }
}

// ---------------- M-step finalize ----------------
__global__ void __launch_bounds__(256) k_mstep() {
    __shared__ float s_w[KCOMP];
    __shared__ float s_ab[2];
    int tid = threadIdx.x;

    if (tid < KCOMP) s_w[tid] = fmaxf(g_stat[tid * NST] * (1.0f / BN), WFLOOR);
    __syncthreads();
    if (tid == 0) {
        float sum = 0.f;
        for (int k = 0; k < KCOMP; k++) sum += s_w[k];
        float sf = WFLOOR * KCOMP;
        float a = (1.0f - sf) / (sum - sf);
        s_ab[0] = a;
        s_ab[1] = WFLOOR * (1.0f - a);
        float ll = 0.f;
        for (int i = 0; i < NBLK_E; i++) ll += g_llp[i];
        g_ll = ll;
    }
    __syncthreads();
    if (tid < KCOMP) g_w[tid] = s_ab[0] * s_w[tid] + s_ab[1];

    for (int idx = tid; idx < KCOMP * LDIM; idx += 256) {
        int k = idx / LDIM, l = idx % LDIM;
        float z = g_stat[k * NST];
        float zi = 1.0f / z;
        float mu = g_stat[k * NST + 1 + l] * zi;
        float sg = fmaxf(g_stat[(KCOMP + k) * NST + 1 + l] * zi - mu * mu, VFLOOR);
        g_mu[idx] = mu;
        g_sig[idx] = sg;
    }
}

// ---------------- output: w | mu | diag-expanded sigma | ll ----------------
__global__ void k_write(float* __restrict__ out) {
    int i = blockIdx.x * 256 + threadIdx.x;
    if (i >= OUT_N) return;
    float v;
    if (i < KCOMP) {
        v = g_w[i];
    } else if (i < KCOMP + KCOMP * LDIM) {
        v = g_mu[i - KCOMP];
    } else if (i < KCOMP + KCOMP * LDIM + KCOMP * LDIM * LDIM) {
        int j = i - (KCOMP + KCOMP * LDIM);
        int k = j / (LDIM * LDIM);
        int rc = j % (LDIM * LDIM);
        int r = rc / LDIM, c = rc % LDIM;
        v = (r == c) ? g_sig[k * LDIM + r] : 0.f;
    } else {
        v = g_ll;
    }
    out[i] = v;
}

extern "C" void kernel_launch(void* const* d_in, const int* in_sizes, int n_in,
                              void* d_out, int out_size) {
    const float* x   = (const float*)d_in[0];
    const float* w0  = (const float*)d_in[1];
    const float* mu0 = (const float*)d_in[2];
    const float* s0  = (const float*)d_in[3];
    float* out = (float*)d_out;

    k_init<<<1, 256>>>(w0, mu0, s0);
    k_prep<<<KCOMP, 32>>>();
    for (int it = 0; it < NITER; it++) {
        k_estep<<<NBLK_E, 128>>>(x);
        k_mstat<<<NBLK_M, 512>>>(x);
        k_reduce<<<128, 256>>>();
        k_mstep<<<1, 256>>>();
        k_prep<<<KCOMP, 32>>>();
    }
    k_write<<<(OUT_N + 255) / 256, 256>>>(out);
}